// round 5
// baseline (speedup 1.0000x reference)
#include <cuda_runtime.h>
#include <mma.h>
#include <math.h>

using namespace nvcuda;

// ---------------------------------------------------------------------------
// MemoryGatedAttention  (B=4, T=S=2048, D=1024, H=16, DH=64, M=64)
// Round 4 (re-bench of R3 after infra failure):
//   tf32 wmma + cp.async double buffering; 128-row flash tile.
// ---------------------------------------------------------------------------

namespace cfg {
constexpr int B  = 4;
constexpr int T  = 2048;
constexpr int S  = 2048;
constexpr int D  = 1024;
constexpr int H  = 16;
constexpr int DH = 64;
constexpr int M  = 64;
constexpr int BT = B * T;
constexpr int FL_LD = 68;          // smem row stride (floats)
// flash smem floats: Ks[2][64][68] + Vs[2][64][68] + Ss[128][68] + stats + idx
constexpr int FL_KS = 2 * 64 * FL_LD;              // 8704
constexpr int FL_VS = 2 * 64 * FL_LD;              // 8704
constexpr int FL_SS = 128 * FL_LD;                 // 8704
constexpr int FL_SMEM_FLOATS = FL_KS + FL_VS + FL_SS + 3 * 128 + 256;
constexpr int FL_SMEM = FL_SMEM_FLOATS * (int)sizeof(float);   // ~107KB
}

// ----------------------------- scratch --------------------------------------
__device__ float g_Q[cfg::B * cfg::T * cfg::D];
__device__ float g_K[cfg::B * cfg::S * cfg::D];
__device__ float g_V[cfg::B * cfg::S * cfg::D];
__device__ float g_O[cfg::B * cfg::T * cfg::D];
__device__ float g_memin[cfg::B * 2 * cfg::D];
__device__ float g_gatevals[cfg::B * cfg::D];
__device__ float g_scale_val;

// ----------------------------- cp.async helpers ------------------------------
__device__ __forceinline__ void cp_async16(void* smem_dst, const void* gmem_src) {
    unsigned sa = (unsigned)__cvta_generic_to_shared(smem_dst);
    asm volatile("cp.async.cg.shared.global [%0], [%1], 16;\n" :: "r"(sa), "l"(gmem_src));
}
__device__ __forceinline__ void cp_commit() {
    asm volatile("cp.async.commit_group;\n");
}
template <int N>
__device__ __forceinline__ void cp_wait() {
    asm volatile("cp.async.wait_group %0;\n" :: "n"(N));
}

// ----------------------------- fragment types --------------------------------
using FragA  = wmma::fragment<wmma::matrix_a, 16, 16, 8, wmma::precision::tf32, wmma::row_major>;
using FragBr = wmma::fragment<wmma::matrix_b, 16, 16, 8, wmma::precision::tf32, wmma::row_major>;
using FragBc = wmma::fragment<wmma::matrix_b, 16, 16, 8, wmma::precision::tf32, wmma::col_major>;
using FragC  = wmma::fragment<wmma::accumulator, 16, 16, 8, float>;

template <typename F>
__device__ __forceinline__ void to_tf32(F& f) {
#pragma unroll
    for (int e = 0; e < f.num_elements; e++) f.x[e] = wmma::__float_to_tf32(f.x[e]);
}

// ----------------------------- means ----------------------------------------
__global__ void __launch_bounds__(256)
mean_kernel(const float* __restrict__ query, const float* __restrict__ memory)
{
    using namespace cfg;
    const int b = blockIdx.y;
    const int d = blockIdx.x * blockDim.x + threadIdx.x;

    const float* qp = query + (size_t)b * T * D + d;
    float s0 = 0.f, s1 = 0.f, s2 = 0.f, s3 = 0.f;
    for (int t = 0; t < T; t += 4) {
        s0 += qp[(size_t)(t + 0) * D];
        s1 += qp[(size_t)(t + 1) * D];
        s2 += qp[(size_t)(t + 2) * D];
        s3 += qp[(size_t)(t + 3) * D];
    }
    g_memin[b * 2 * D + d] = ((s0 + s1) + (s2 + s3)) * (1.0f / T);

    const float* mp = memory + (size_t)b * M * D + d;
    float u0 = 0.f, u1 = 0.f;
    for (int m = 0; m < M; m += 2) {
        u0 += mp[(size_t)(m + 0) * D];
        u1 += mp[(size_t)(m + 1) * D];
    }
    g_memin[b * 2 * D + D + d] = (u0 + u1) * (1.0f / M);
}

// ----------------------------- gate ------------------------------------------
__global__ void __launch_bounds__(256)
gate_vals_kernel(const float* __restrict__ Wg, const float* __restrict__ bg)
{
    using namespace cfg;
    const int b = blockIdx.y;
    const int j = blockIdx.x * blockDim.x + threadIdx.x;
    const float* mi = g_memin + b * 2 * D;

    float a0 = 0.f, a1 = 0.f, a2 = 0.f, a3 = 0.f;
    for (int i = 0; i < 2 * D; i += 4) {
        a0 += mi[i + 0] * Wg[(size_t)(i + 0) * D + j];
        a1 += mi[i + 1] * Wg[(size_t)(i + 1) * D + j];
        a2 += mi[i + 2] * Wg[(size_t)(i + 2) * D + j];
        a3 += mi[i + 3] * Wg[(size_t)(i + 3) * D + j];
    }
    float acc = bg[j] + ((a0 + a1) + (a2 + a3));
    g_gatevals[b * D + j] = 1.0f / (1.0f + expf(-acc));
}

__global__ void gate_reduce_kernel()
{
    using namespace cfg;
    __shared__ float red[1024];
    const int t = threadIdx.x;
    red[t] = g_gatevals[t] + g_gatevals[t + 1024] +
             g_gatevals[t + 2048] + g_gatevals[t + 3072];
    __syncthreads();
    for (int s = 512; s > 0; s >>= 1) {
        if (t < s) red[t] += red[t + s];
        __syncthreads();
    }
    if (t == 0) g_scale_val = red[0] * (1.0f / (B * D)) * 0.125f;
}

// ----------------------------- tf32 GEMM body (double-buffered) --------------
// C = A[8192,1024] @ W[1024,1024] + bias.  128x128x16 tile, 8 warps (2x4).
__device__ __forceinline__ void gemm_body(
    const float* __restrict__ A, const float* __restrict__ W,
    const float* __restrict__ bias, float* __restrict__ C)
{
    using namespace cfg;
    __shared__ float As[2][128][20];
    __shared__ float Bs[2][16][132];
    __shared__ float idxm[256];

    const int tid = threadIdx.x;
    const int warpId = tid >> 5;
    const int wr = warpId >> 2;
    const int wc = warpId & 3;
    const int m0 = blockIdx.y * 128;
    const int n0 = blockIdx.x * 128;

    idxm[tid] = (float)(tid & 15);

    const int aRow = tid >> 2, aC = (tid & 3) * 4;
    const int bRow = tid >> 5, bC = (tid & 31) * 4;

    auto issue_tile = [&](int k0, int buf) {
#pragma unroll
        for (int t = 0; t < 2; t++) {
            int r = aRow + t * 64;
            cp_async16(&As[buf][r][aC], A + (size_t)(m0 + r) * D + k0 + aC);
        }
#pragma unroll
        for (int t = 0; t < 2; t++) {
            int r = bRow + t * 8;
            cp_async16(&Bs[buf][r][bC], W + (size_t)(k0 + r) * D + n0 + bC);
        }
        cp_commit();
    };

    FragC acc[4][2];
#pragma unroll
    for (int i = 0; i < 4; i++)
#pragma unroll
        for (int j = 0; j < 2; j++) wmma::fill_fragment(acc[i][j], 0.f);

    issue_tile(0, 0);
    __syncthreads();                 // idxm visible
    FragC colidx;
    wmma::load_matrix_sync(colidx, idxm, 16, wmma::mem_row_major);

    constexpr int NIT = cfg::D / 16;     // 64
    for (int kt = 0; kt < NIT; kt++) {
        const int buf = kt & 1;
        if (kt + 1 < NIT) issue_tile((kt + 1) * 16, buf ^ 1);
        if (kt + 1 < NIT) cp_wait<1>(); else cp_wait<0>();
        __syncthreads();

#pragma unroll
        for (int kk = 0; kk < 2; kk++) {
            FragA af[4];
#pragma unroll
            for (int i = 0; i < 4; i++) {
                wmma::load_matrix_sync(af[i], &As[buf][64 * wr + 16 * i][8 * kk], 20);
                to_tf32(af[i]);
            }
            FragBr bf[2];
#pragma unroll
            for (int j = 0; j < 2; j++) {
                wmma::load_matrix_sync(bf[j], &Bs[buf][8 * kk][32 * wc + 16 * j], 132);
                to_tf32(bf[j]);
            }
#pragma unroll
            for (int i = 0; i < 4; i++)
#pragma unroll
                for (int j = 0; j < 2; j++)
                    wmma::mma_sync(acc[i][j], af[i], bf[j], acc[i][j]);
        }
        __syncthreads();             // readers done before buf is overwritten
    }

#pragma unroll
    for (int i = 0; i < 4; i++)
#pragma unroll
        for (int j = 0; j < 2; j++) {
            const int nbase = n0 + 32 * wc + 16 * j;
#pragma unroll
            for (int e = 0; e < 8; e++)
                acc[i][j].x[e] += __ldg(&bias[nbase + (int)colidx.x[e]]);
            wmma::store_matrix_sync(
                C + (size_t)(m0 + 64 * wr + 16 * i) * D + nbase,
                acc[i][j], D, wmma::mem_row_major);
        }
}

// fused QKV projection: blockIdx.z selects input/weight/output
__global__ void __launch_bounds__(256)
gemm_qkv_kernel(const float* __restrict__ q, const float* __restrict__ k,
                const float* __restrict__ v,
                const float* __restrict__ Wq, const float* __restrict__ Wk,
                const float* __restrict__ Wv,
                const float* __restrict__ bq, const float* __restrict__ bk,
                const float* __restrict__ bv,
                float* __restrict__ oq, float* __restrict__ ok,
                float* __restrict__ ov)
{
    const float *A, *W, *bias; float* C;
    if (blockIdx.z == 0)      { A = q; W = Wq; bias = bq; C = oq; }
    else if (blockIdx.z == 1) { A = k; W = Wk; bias = bk; C = ok; }
    else                      { A = v; W = Wv; bias = bv; C = ov; }
    gemm_body(A, W, bias, C);
}

__global__ void __launch_bounds__(256)
gemm_single_kernel(const float* __restrict__ A, const float* __restrict__ W,
                   const float* __restrict__ bias, float* __restrict__ C)
{
    gemm_body(A, W, bias, C);
}

// ----------------------------- tf32 flash attention --------------------------
// grid (T/128, H, B), 256 threads = 8 warps; warp w owns rows 16w..16w+15.
// K/V tiles 64 keys, double-buffered via cp.async.
__global__ void __launch_bounds__(256)
flash_tf32_kernel(const float* __restrict__ Q, const float* __restrict__ K,
                  const float* __restrict__ V, float* __restrict__ O)
{
    using namespace cfg;
    extern __shared__ float sm[];
    float* Ks     = sm;                               // [2][64][FL_LD]
    float* Vs     = sm + FL_KS;                       // [2][64][FL_LD]
    float* Ss     = sm + FL_KS + FL_VS;               // [128][FL_LD]
    float* m_s    = Ss + FL_SS;                       // [128]
    float* l_s    = m_s + 128;
    float* corr_s = l_s + 128;
    float* idxm   = corr_s + 128;                     // [256]

    const int b = blockIdx.z, h = blockIdx.y, q0 = blockIdx.x * 128;
    const int tid = threadIdx.x;
    const int w = tid >> 5;                           // warp -> rows 16w
    const float gscale = g_scale_val;

    const float* Kp = K + (size_t)b * S * D + h * DH;
    const float* Vp = V + (size_t)b * S * D + h * DH;

    idxm[tid] = (float)(tid >> 4);
    if (tid < 128) { m_s[tid] = -INFINITY; l_s[tid] = 0.f; }

    // stage Q tile (128 x 64) into Ss: 2 threads/row, 32 floats each
    {
        const int r = tid >> 1, half = tid & 1;
        const float* src = Q + (size_t)(b * T + q0 + r) * D + h * DH + half * 32;
        float* dst = &Ss[r * FL_LD + half * 32];
#pragma unroll
        for (int jj = 0; jj < 8; jj++)
            *(float4*)(dst + jj * 4) = *(const float4*)(src + jj * 4);
    }
    __syncthreads();

    FragC rowidx;
    wmma::load_matrix_sync(rowidx, idxm, 16, wmma::mem_row_major);

    FragA qf[8];
#pragma unroll
    for (int k = 0; k < 8; k++) {
        wmma::load_matrix_sync(qf[k], &Ss[(16 * w) * FL_LD + 8 * k], FL_LD);
        to_tf32(qf[k]);
    }
    FragC of[4];
#pragma unroll
    for (int j = 0; j < 4; j++) wmma::fill_fragment(of[j], 0.f);
    __syncthreads();                 // Q staging reads finished before Ss reuse

    // K/V tile loader: 64 rows x 64 floats each => 4 chunks/thread/array
    auto issue_kv = [&](int s0, int buf) {
        float* kb = Ks + buf * 64 * FL_LD;
        float* vb = Vs + buf * 64 * FL_LD;
#pragma unroll
        for (int t = 0; t < 4; t++) {
            int c = tid + t * 256;                   // 0..1023
            int row = c >> 4, col = (c & 15) * 4;
            cp_async16(&kb[row * FL_LD + col], Kp + (size_t)(s0 + row) * D + col);
        }
#pragma unroll
        for (int t = 0; t < 4; t++) {
            int c = tid + t * 256;
            int row = c >> 4, col = (c & 15) * 4;
            cp_async16(&vb[row * FL_LD + col], Vp + (size_t)(s0 + row) * D + col);
        }
        cp_commit();
    };

    issue_kv(0, 0);

    constexpr int NT = cfg::S / 64;                  // 32
    for (int it = 0; it < NT; it++) {
        const int buf = it & 1;
        if (it + 1 < NT) issue_kv((it + 1) * 64, buf ^ 1);
        if (it + 1 < NT) cp_wait<1>(); else cp_wait<0>();
        __syncthreads();

        // ---- S = Q K^T
        const float* kb = Ks + buf * 64 * FL_LD;
        FragC sf[4];
#pragma unroll
        for (int j = 0; j < 4; j++) wmma::fill_fragment(sf[j], 0.f);
#pragma unroll
        for (int k = 0; k < 8; k++) {
#pragma unroll
            for (int j = 0; j < 4; j++) {
                FragBc bf;
                wmma::load_matrix_sync(bf, &kb[(16 * j) * FL_LD + 8 * k], FL_LD);
                to_tf32(bf);
                wmma::mma_sync(sf[j], qf[k], bf, sf[j]);
            }
        }
#pragma unroll
        for (int j = 0; j < 4; j++)
            wmma::store_matrix_sync(&Ss[(16 * w) * FL_LD + 16 * j], sf[j],
                                    FL_LD, wmma::mem_row_major);
        __syncthreads();

        // ---- online softmax: 2 threads per row, 32 cols each
        {
            const int r = tid >> 1, half = tid & 1;
            float* row = &Ss[r * FL_LD + half * 32];
            float v[32];
#pragma unroll
            for (int jj = 0; jj < 8; jj++) {
                float4 x = *(float4*)(row + jj * 4);
                v[jj * 4 + 0] = x.x * gscale; v[jj * 4 + 1] = x.y * gscale;
                v[jj * 4 + 2] = x.z * gscale; v[jj * 4 + 3] = x.w * gscale;
            }
            float mx = v[0];
#pragma unroll
            for (int i = 1; i < 32; i++) mx = fmaxf(mx, v[i]);
            mx = fmaxf(mx, __shfl_xor_sync(0xffffffffu, mx, 1));

            const float mold = m_s[r];
            const float nm = fmaxf(mold, mx);
            float sum = 0.f;
#pragma unroll
            for (int i = 0; i < 32; i++) { v[i] = __expf(v[i] - nm); sum += v[i]; }
#pragma unroll
            for (int jj = 0; jj < 8; jj++)
                *(float4*)(row + jj * 4) =
                    make_float4(v[jj * 4 + 0], v[jj * 4 + 1],
                                v[jj * 4 + 2], v[jj * 4 + 3]);
            sum += __shfl_xor_sync(0xffffffffu, sum, 1);
            if (half == 0) {
                float corr = __expf(mold - nm);
                l_s[r] = l_s[r] * corr + sum;
                m_s[r] = nm;
                corr_s[r] = corr;
            }
        }
        __syncthreads();

        // ---- rescale O accumulators
#pragma unroll
        for (int j = 0; j < 4; j++)
#pragma unroll
            for (int e = 0; e < 8; e++)
                of[j].x[e] *= corr_s[16 * w + (int)rowidx.x[e]];

        // ---- O += P V
        const float* vb = Vs + buf * 64 * FL_LD;
#pragma unroll
        for (int k = 0; k < 8; k++) {
            FragA pf;
            wmma::load_matrix_sync(pf, &Ss[(16 * w) * FL_LD + 8 * k], FL_LD);
            to_tf32(pf);
#pragma unroll
            for (int j = 0; j < 4; j++) {
                FragBr vf;
                wmma::load_matrix_sync(vf, &vb[(8 * k) * FL_LD + 16 * j], FL_LD);
                to_tf32(vf);
                wmma::mma_sync(of[j], pf, vf, of[j]);
            }
        }
        __syncthreads();   // Ss / Vs[buf] free before next tile's writes
    }

    // epilogue
    if (tid < 128) corr_s[tid] = 1.0f / l_s[tid];
    __syncthreads();
#pragma unroll
    for (int j = 0; j < 4; j++) {
#pragma unroll
        for (int e = 0; e < 8; e++)
            of[j].x[e] *= corr_s[16 * w + (int)rowidx.x[e]];
        wmma::store_matrix_sync(
            O + (size_t)(b * T + q0 + 16 * w) * D + h * DH + 16 * j,
            of[j], D, wmma::mem_row_major);
    }
}

// ----------------------------- launch ----------------------------------------
extern "C" void kernel_launch(void* const* d_in, const int* in_sizes, int n_in,
                              void* d_out, int out_size)
{
    using namespace cfg;
    (void)in_sizes; (void)n_in; (void)out_size;

    const float* query  = (const float*)d_in[0];
    const float* key    = (const float*)d_in[1];
    const float* value  = (const float*)d_in[2];
    const float* memory = (const float*)d_in[3];
    const float* Wq = (const float*)d_in[4];
    const float* bq = (const float*)d_in[5];
    const float* Wk = (const float*)d_in[6];
    const float* bk = (const float*)d_in[7];
    const float* Wv = (const float*)d_in[8];
    const float* bv = (const float*)d_in[9];
    const float* Wo = (const float*)d_in[10];
    const float* bo = (const float*)d_in[11];
    const float* Wg = (const float*)d_in[12];
    const float* bg = (const float*)d_in[13];
    float* out = (float*)d_out;

    void *pQ, *pK, *pV, *pO;
    cudaGetSymbolAddress(&pQ, g_Q);
    cudaGetSymbolAddress(&pK, g_K);
    cudaGetSymbolAddress(&pV, g_V);
    cudaGetSymbolAddress(&pO, g_O);

    cudaFuncSetAttribute(flash_tf32_kernel,
                         cudaFuncAttributeMaxDynamicSharedMemorySize, FL_SMEM);

    // gate path
    mean_kernel<<<dim3(D / 256, B), 256>>>(query, memory);
    gate_vals_kernel<<<dim3(D / 256, B), 256>>>(Wg, bg);
    gate_reduce_kernel<<<1, 1024>>>();

    // fused QKV projections
    gemm_qkv_kernel<<<dim3(D / 128, BT / 128, 3), 256>>>(
        query, key, value, Wq, Wk, Wv, bq, bk, bv,
        (float*)pQ, (float*)pK, (float*)pV);

    // attention
    flash_tf32_kernel<<<dim3(T / 128, H, B), 256, FL_SMEM>>>(
        (const float*)pQ, (const float*)pK, (const float*)pV, (float*)pO);

    // output projection -> d_out
    gemm_single_kernel<<<dim3(D / 128, BT / 128), 256>>>(
        (const float*)pO, Wo, bo, out);
}